// round 3
// baseline (speedup 1.0000x reference)
#include <cuda_runtime.h>
#include <math.h>

#define BSZ 256
#define IND 64
#define HID 128
#define NB 50
#define S1 51
#define ROWS (S1 * S1)          // 2601
#define ST 132                  // padded segment stride (floats)
#define SEGF (129 * ST)         // 17028 floats per segment array
#define NTHR 512
#define NWARP 16
#define PI_D 3.14159265358979323846

// smem float layout
#define OFF_META  (2 * SEGF)            // 2601 * 4 floats (s, wt, g, pad)
#define OFF_B     (OFF_META + ROWS * 4) // base_s 128
#define OFF_W0    (OFF_B + 128)
#define OFF_BP    (OFF_W0 + 128)
#define OFF_STEPS (OFF_BP + 128)        // 64
#define OFF_CC    (OFF_STEPS + 64)      // 64
#define OFF_RED   (OFF_CC + 64)         // 32
#define OFF_O     (OFF_RED + 32)        // 4
#define OFF_MI    (OFF_O + 4)           // 128 ints
#define OFF_H     (OFF_MI + 128)        // 64
#define SMEM_FLOATS (OFF_H + 64)        // ~45200 floats = ~177 KB

__device__ float g_steps[S1];
__device__ float g_cc[S1];
__device__ float g_xmax;
__device__ int   g_iperm[HID];
__device__ int   g_npos;

// ===================== prep =====================
__global__ void prep_kernel(const float* __restrict__ x, const float* __restrict__ iw2) {
    __shared__ float st_s[S1];
    __shared__ double part[256];
    __shared__ float red[256];
    int tx = threadIdx.x;
    if (tx < S1) {
        double st = cos((double)tx * PI_D / (double)NB);
        st_s[tx] = (float)st;
        g_steps[tx] = (float)st;
    }
    double p = 0.0;
    if (tx < 255) {
        int c = tx / 5, u = tx % 5;
        for (int ie = u; ie < 26; ie += 5) {
            int i = 2 * ie;
            double W = (i == 0) ? 1.0 : 2.0 / (1.0 - (double)i * (double)i);
            double l;
            if (c == 0) l = 0.5;
            else {
                l = cos((double)i * (double)c * PI_D / (double)NB);
                if (c == NB) l *= 0.5;
            }
            p += l * (2.0 / (double)NB) * W;
        }
    }
    part[tx] = p;
    __syncthreads();
    if (tx < S1) {
        double s = 0.0;
        for (int u = 0; u < 5; u++) s += part[tx * 5 + u];
        g_cc[tx] = (float)s;
    }
    float mx = -3.0e38f;
    if (tx < BSZ) {
        float xb = x[tx];
        for (int i = 0; i < S1; i++)
            mx = fmaxf(mx, xb * (st_s[i] + 1.0f) * 0.5f);
    }
    red[tx] = mx;
    __syncthreads();
    for (int o = 128; o > 0; o >>= 1) {
        if (tx < o) red[tx] = fmaxf(red[tx], red[tx + o]);
        __syncthreads();
    }
    if (tx == 0) {
        g_xmax = red[0] + 10.0f;
        int P = 0;
        for (int k = 0; k < HID; k++) if (iw2[k] >= 0.0f) g_iperm[k] = P++;
        g_npos = P;
        for (int k = 0; k < HID; k++) if (iw2[k] < 0.0f)  g_iperm[k] = P++;
    }
}

// ===================== main =====================
__global__ void __launch_bounds__(NTHR, 1)
main_kernel(const float* __restrict__ x,   const float* __restrict__ h,
            const float* __restrict__ iw0, const float* __restrict__ ib0,
            const float* __restrict__ iw1, const float* __restrict__ ib1,
            const float* __restrict__ iw2, const float* __restrict__ ib2,
            const float* __restrict__ nw0, const float* __restrict__ nb0,
            const float* __restrict__ nw1, const float* __restrict__ nb1,
            const float* __restrict__ nw2, const float* __restrict__ nb2,
            float* __restrict__ out)
{
    extern __shared__ float sm[];
    float* Aseg    = sm;
    float* Bseg    = sm + SEGF;
    float* meta    = sm + OFF_META;
    float* base_s  = sm + OFF_B;
    float* w0_s    = sm + OFF_W0;
    float* bp_s    = sm + OFF_BP;
    float* steps_s = sm + OFF_STEPS;
    float* cc_s    = sm + OFF_CC;
    float* red_s   = sm + OFF_RED;
    float* o_s     = sm + OFF_O;
    int*   mi_s    = (int*)(sm + OFF_MI);
    float* h_s     = sm + OFF_H;

    const int tx = threadIdx.x;
    const int warp = tx >> 5, lane = tx & 31;
    const int b  = blockIdx.x;
    const float xb   = x[b];
    const float xmax = g_xmax;
    const float ib2v = ib2[0];
    const int   npos = g_npos;

    if (tx < IND - 1) h_s[tx] = h[b * (IND - 1) + tx];
    if (tx < S1) { steps_s[tx] = g_steps[tx]; cc_s[tx] = g_cc[tx]; }
    __syncthreads();

    // ---- base, breakpoints (tx<128) | nmlp layer0 (128<=tx<256) ----
    if (tx < HID) {
        float acc = ib0[tx];
        #pragma unroll 7
        for (int d = 0; d < IND - 1; ++d)
            acc = fmaf(h_s[d], iw0[(d + 1) * HID + tx], acc);
        base_s[tx] = acc;
        float w0m = iw0[tx];
        w0_s[tx] = w0m;
        float ss;
        if (w0m != 0.0f) ss = -acc / w0m;
        else ss = (acc > 0.0f) ? __int_as_float(0x7f800000) : __int_as_float(0xff800000);
        bp_s[tx] = ss;
        mi_s[tx] = tx;
    } else if (tx < 256) {
        int k = tx - 128;
        float acc = nb0[k];
        #pragma unroll 7
        for (int d = 0; d < IND - 1; ++d)
            acc = fmaf(h_s[d], nw0[d * HID + k], acc);
        meta[k] = fmaxf(acc, 0.0f);          // a_s scratch in meta region
    }
    __syncthreads();
    if (tx < HID) {
        float acc = nb1[tx];
        #pragma unroll 8
        for (int m = 0; m < HID; ++m)
            acc = fmaf(meta[m], nw1[m * HID + tx], acc);
        meta[128 + tx] = fmaxf(acc, 0.0f);   // a2_s scratch
    }
    __syncthreads();
    if (tx < 256) {
        int o  = tx >> 7;
        int n2 = tx & 127;
        float p = meta[128 + n2] * nw2[n2 * 2 + o];
        #pragma unroll
        for (int off = 16; off >= 1; off >>= 1)
            p += __shfl_xor_sync(0xffffffffu, p, off);
        if ((tx & 31) == 0) red_s[16 + (tx >> 5)] = p;
    }
    __syncthreads();
    if (tx == 0)   o_s[0] = nb2[0] + ((red_s[16] + red_s[17]) + (red_s[18] + red_s[19]));
    if (tx == 128) o_s[1] = nb2[1] + ((red_s[20] + red_s[21]) + (red_s[22] + red_s[23]));

    // ---- bitonic sort of breakpoints ----
    __syncthreads();
    for (int kk = 2; kk <= 128; kk <<= 1) {
        for (int j = kk >> 1; j > 0; j >>= 1) {
            if (tx < 128) {
                int ixj = tx ^ j;
                if (ixj > tx) {
                    float a = bp_s[tx], c = bp_s[ixj];
                    bool up = ((tx & kk) == 0);
                    if ((a > c) == up) {
                        bp_s[tx] = c; bp_s[ixj] = a;
                        int t2 = mi_s[tx]; mi_s[tx] = mi_s[ixj]; mi_s[ixj] = t2;
                    }
                }
            }
            __syncthreads();
        }
    }

    // ---- build segment prefix vectors (256 builder threads) ----
    if (tx < 256) {
        int k = tx & 127;
        bool isA = (tx < 128);
        int kp = g_iperm[k];
        float w2k = iw2[k];
        float* seg = isA ? Aseg : Bseg;
        float r = isA ? 0.0f : ib1[k] * w2k;
        #pragma unroll 4
        for (int g = 128; g >= 1; --g) {
            seg[g * ST + kp] = r;
            int m = mi_s[g - 1];
            float w0m = w0_s[m];
            float wv = iw1[m * HID + k] * w2k;
            float coef = isA ? w0m : base_s[m];
            coef = (w0m <= 0.0f) ? coef : 0.0f;
            r = fmaf(coef, wv, r);
        }
        seg[kp] = r;
        r = 0.0f;
        #pragma unroll 4
        for (int g = 0; g < 128; ++g) {
            int m = mi_s[g];
            float w0m = w0_s[m];
            float wv = iw1[m * HID + k] * w2k;
            float coef = isA ? w0m : base_s[m];
            coef = (w0m > 0.0f) ? coef : 0.0f;
            r = fmaf(coef, wv, r);
            seg[(g + 1) * ST + kp] += r;
        }
    }
    __syncthreads();

    // ---- meta precompute: (s, wt, g) per point ----
    for (int p = tx; p < ROWS; p += NTHR) {
        int i = p / S1, j = p - i * S1;
        float tbi = xb * (steps_s[i] + 1.0f) * 0.5f;
        float rem = xmax - tbi;
        float s = fmaf(rem, (steps_s[j] + 1.0f) * 0.5f, tbi);
        float wt = cc_s[i] * cc_s[j] * rem * 0.5f;
        int g = 0;
        #pragma unroll
        for (int stp = 64; stp >= 1; stp >>= 1) {
            int cand = g + stp;
            if (cand <= 128 && bp_s[cand - 1] < s) g = cand;
        }
        *(float4*)(meta + 4 * p) = make_float4(s, wt, __int_as_float(g), 0.0f);
    }
    __syncthreads();

    // ---- quad loop: warp-per-point, lanes over k, 4-pt ILP ----
    const int lane4 = lane * 4;
    const bool mx0 = (lane4 + 0) < npos;
    const bool mx1 = (lane4 + 1) < npos;
    const bool mx2 = (lane4 + 2) < npos;
    const bool mx3 = (lane4 + 3) < npos;

    const int CH = (ROWS + NWARP - 1) / NWARP;          // 163
    const int start = warp * CH;
    const int end = (start + CH < ROWS) ? start + CH : ROWS;

    float acc = 0.0f;
    int p = start;
    for (; p + 4 <= end; p += 4) {
        float4 m[4];
        float pr[4];
        #pragma unroll
        for (int u = 0; u < 4; u++) m[u] = *(const float4*)(meta + 4 * (p + u));
        #pragma unroll
        for (int u = 0; u < 4; u++) {
            int g = __float_as_int(m[u].z);
            const float* ap = sm + g * ST + lane4;
            float4 a = *(const float4*)ap;
            float4 bb = *(const float4*)(ap + SEGF);
            float s = m[u].x;
            float t0 = fmaf(s, a.x, bb.x);
            float t1 = fmaf(s, a.y, bb.y);
            float t2 = fmaf(s, a.z, bb.z);
            float t3 = fmaf(s, a.w, bb.w);
            float v0 = mx0 ? fmaxf(t0, 0.0f) : fminf(t0, 0.0f);
            float v1 = mx1 ? fmaxf(t1, 0.0f) : fminf(t1, 0.0f);
            float v2 = mx2 ? fmaxf(t2, 0.0f) : fminf(t2, 0.0f);
            float v3 = mx3 ? fmaxf(t3, 0.0f) : fminf(t3, 0.0f);
            pr[u] = (v0 + v1) + (v2 + v3);
        }
        #pragma unroll
        for (int off = 16; off >= 1; off >>= 1) {
            #pragma unroll
            for (int u = 0; u < 4; u++)
                pr[u] += __shfl_xor_sync(0xffffffffu, pr[u], off);
        }
        #pragma unroll
        for (int u = 0; u < 4; u++) {
            float z = pr[u] + ib2v;
            float f = (z > 0.0f) ? (z + 1.0f) : expf(z);
            acc = fmaf(f, m[u].y, acc);
        }
    }
    for (; p < end; ++p) {
        float4 mu = *(const float4*)(meta + 4 * p);
        int g = __float_as_int(mu.z);
        const float* ap = sm + g * ST + lane4;
        float4 a = *(const float4*)ap;
        float4 bb = *(const float4*)(ap + SEGF);
        float s = mu.x;
        float t0 = fmaf(s, a.x, bb.x);
        float t1 = fmaf(s, a.y, bb.y);
        float t2 = fmaf(s, a.z, bb.z);
        float t3 = fmaf(s, a.w, bb.w);
        float v0 = mx0 ? fmaxf(t0, 0.0f) : fminf(t0, 0.0f);
        float v1 = mx1 ? fmaxf(t1, 0.0f) : fminf(t1, 0.0f);
        float v2 = mx2 ? fmaxf(t2, 0.0f) : fminf(t2, 0.0f);
        float v3 = mx3 ? fmaxf(t3, 0.0f) : fminf(t3, 0.0f);
        float pr = (v0 + v1) + (v2 + v3);
        #pragma unroll
        for (int off = 16; off >= 1; off >>= 1)
            pr += __shfl_xor_sync(0xffffffffu, pr, off);
        float z = pr + ib2v;
        float f = (z > 0.0f) ? (z + 1.0f) : expf(z);
        acc = fmaf(f, mu.y, acc);
    }

    // ---- reduce 16 warp totals (acc identical across lanes) ----
    if (lane == 0) red_s[warp] = acc;
    __syncthreads();
    if (tx == 0) {
        float sum = 0.0f;
        #pragma unroll
        for (int w = 0; w < NWARP; w++) sum += red_s[w];
        float outer = sum * xb * 0.5f;
        out[b] = expf(o_s[1]) * outer + o_s[0];
    }
}

// ===================== launch =====================
extern "C" void kernel_launch(void* const* d_in, const int* in_sizes, int n_in,
                              void* d_out, int out_size) {
    const float* x   = (const float*)d_in[0];
    const float* h   = (const float*)d_in[1];
    const float* iw0 = (const float*)d_in[2];
    const float* ib0 = (const float*)d_in[3];
    const float* iw1 = (const float*)d_in[4];
    const float* ib1 = (const float*)d_in[5];
    const float* iw2 = (const float*)d_in[6];
    const float* ib2 = (const float*)d_in[7];
    const float* nw0 = (const float*)d_in[8];
    const float* nb0 = (const float*)d_in[9];
    const float* nw1 = (const float*)d_in[10];
    const float* nb1 = (const float*)d_in[11];
    const float* nw2 = (const float*)d_in[12];
    const float* nb2 = (const float*)d_in[13];
    float* out = (float*)d_out;
    (void)in_sizes; (void)n_in; (void)out_size;

    const int smem_bytes = SMEM_FLOATS * (int)sizeof(float);
    cudaFuncSetAttribute(main_kernel,
                         cudaFuncAttributeMaxDynamicSharedMemorySize, smem_bytes);

    prep_kernel<<<1, 256>>>(x, iw2);
    main_kernel<<<BSZ, NTHR, smem_bytes>>>(x, h, iw0, ib0, iw1, ib1, iw2, ib2,
                                           nw0, nb0, nw1, nb1, nw2, nb2, out);
}

// round 4
// speedup vs baseline: 1.0948x; 1.0948x over previous
#include <cuda_runtime.h>
#include <math.h>

#define BSZ 256
#define IND 64
#define HID 128
#define NB 50
#define S1 51
#define ROWS (S1 * S1)          // 2601
#define ST 140                  // padded segment stride (floats); 136 used + pad
#define NK4 34                  // 136/4 float4 steps per point
#define SEGF (129 * ST)         // 18060 floats per segment array
#define NTHR 512
#define PI_D 3.14159265358979323846

// smem float layout
#define OFF_SORT  (2 * SEGF)              // sorted meta: 2601 * float4
#define OFF_RES   (OFF_SORT + ROWS * 4)   // 2604 floats (also nmlp scratch)
#define OFF_B     (OFF_RES + 2604)        // base 128
#define OFF_W0    (OFF_B + 128)
#define OFF_BP    (OFF_W0 + 128)
#define OFF_STEPS (OFF_BP + 128)          // 64
#define OFF_CC    (OFF_STEPS + 64)        // 64
#define OFF_RED   (OFF_CC + 64)           // 512
#define OFF_O     (OFF_RED + 512)         // 4
#define OFF_MI    (OFF_O + 4)             // 128 ints
#define OFF_CNT   (OFF_MI + 128)          // 132 ints
#define OFF_OFFS  (OFF_CNT + 132)         // 132 ints
#define OFF_H     (OFF_OFFS + 132)        // 64
#define SMEM_FLOATS (OFF_H + 64)          // ~50612 floats ≈ 198 KB

__device__ float g_steps[S1];
__device__ float g_cc[S1];
__device__ float g_xmax;
__device__ int   g_iperm[HID];
__device__ int   g_npos;    // #k with iw2 >= 0
__device__ int   g_nposp;   // npos rounded up to mult of 4

// ===================== prep =====================
__global__ void prep_kernel(const float* __restrict__ x, const float* __restrict__ iw2) {
    __shared__ float st_s[S1];
    __shared__ double part[256];
    __shared__ float red[256];
    int tx = threadIdx.x;
    if (tx < S1) {
        double st = cos((double)tx * PI_D / (double)NB);
        st_s[tx] = (float)st;
        g_steps[tx] = (float)st;
    }
    double p = 0.0;
    if (tx < 255) {
        int c = tx / 5, u = tx % 5;
        for (int ie = u; ie < 26; ie += 5) {
            int i = 2 * ie;
            double W = (i == 0) ? 1.0 : 2.0 / (1.0 - (double)i * (double)i);
            double l;
            if (c == 0) l = 0.5;
            else {
                l = cos((double)i * (double)c * PI_D / (double)NB);
                if (c == NB) l *= 0.5;
            }
            p += l * (2.0 / (double)NB) * W;
        }
    }
    part[tx] = p;
    __syncthreads();
    if (tx < S1) {
        double s = 0.0;
        for (int u = 0; u < 5; u++) s += part[tx * 5 + u];
        g_cc[tx] = (float)s;
    }
    float mx = -3.0e38f;
    if (tx < BSZ) {
        float xb = x[tx];
        for (int i = 0; i < S1; i++)
            mx = fmaxf(mx, xb * (st_s[i] + 1.0f) * 0.5f);
    }
    red[tx] = mx;
    __syncthreads();
    for (int o = 128; o > 0; o >>= 1) {
        if (tx < o) red[tx] = fmaxf(red[tx], red[tx + o]);
        __syncthreads();
    }
    if (tx == 0) {
        g_xmax = red[0] + 10.0f;
        int P = 0;
        for (int k = 0; k < HID; k++) if (iw2[k] >= 0.0f) g_iperm[k] = P++;
        g_npos = P;
        int Pp = (P + 3) & ~3;
        g_nposp = Pp;
        int Q = Pp;
        for (int k = 0; k < HID; k++) if (iw2[k] < 0.0f)  g_iperm[k] = Q++;
    }
}

// ===================== main: one block per batch element =====================
__global__ void __launch_bounds__(NTHR, 1)
main_kernel(const float* __restrict__ x,   const float* __restrict__ h,
            const float* __restrict__ iw0, const float* __restrict__ ib0,
            const float* __restrict__ iw1, const float* __restrict__ ib1,
            const float* __restrict__ iw2, const float* __restrict__ ib2,
            const float* __restrict__ nw0, const float* __restrict__ nb0,
            const float* __restrict__ nw1, const float* __restrict__ nb1,
            const float* __restrict__ nw2, const float* __restrict__ nb2,
            float* __restrict__ out)
{
    extern __shared__ float sm[];
    float* Aseg    = sm;                    // Bseg = Aseg + SEGF (contiguous)
    float* sorted  = sm + OFF_SORT;
    float* res     = sm + OFF_RES;
    float* base_s  = sm + OFF_B;
    float* w0_s    = sm + OFF_W0;
    float* bp_s    = sm + OFF_BP;
    float* steps_s = sm + OFF_STEPS;
    float* cc_s    = sm + OFF_CC;
    float* red_s   = sm + OFF_RED;
    float* o_s     = sm + OFF_O;
    int*   mi_s    = (int*)(sm + OFF_MI);
    int*   cnt_s   = (int*)(sm + OFF_CNT);
    int*   offs_s  = (int*)(sm + OFF_OFFS);
    float* h_s     = sm + OFF_H;

    const int tx = threadIdx.x;
    const int b  = blockIdx.x;
    const float xb   = x[b];
    const float xmax = g_xmax;
    const float ib2v = ib2[0];
    const int   npos  = g_npos;
    const int   nposp = g_nposp;

    if (tx < IND - 1) h_s[tx] = h[b * (IND - 1) + tx];
    if (tx < S1) { steps_s[tx] = g_steps[tx]; cc_s[tx] = g_cc[tx]; }
    if (tx >= 256 && tx < 256 + 132) { cnt_s[tx - 256] = 0; }
    __syncthreads();

    // ---- base/breakpoints (tx<128) | nmlp layer0 (128..255), scratch in res ----
    if (tx < HID) {
        float acc = ib0[tx];
        #pragma unroll 7
        for (int d = 0; d < IND - 1; ++d)
            acc = fmaf(h_s[d], iw0[(d + 1) * HID + tx], acc);
        base_s[tx] = acc;
        float w0m = iw0[tx];
        w0_s[tx] = w0m;
        float ss;
        if (w0m != 0.0f) ss = -acc / w0m;
        else ss = (acc > 0.0f) ? __int_as_float(0x7f800000) : __int_as_float(0xff800000);
        bp_s[tx] = ss;
        mi_s[tx] = tx;
    } else if (tx < 256) {
        int k = tx - 128;
        float acc = nb0[k];
        #pragma unroll 7
        for (int d = 0; d < IND - 1; ++d)
            acc = fmaf(h_s[d], nw0[d * HID + k], acc);
        res[k] = fmaxf(acc, 0.0f);
    }
    __syncthreads();
    if (tx < HID) {
        float acc = nb1[tx];
        #pragma unroll 8
        for (int m = 0; m < HID; ++m)
            acc = fmaf(res[m], nw1[m * HID + tx], acc);
        res[128 + tx] = fmaxf(acc, 0.0f);
    }
    __syncthreads();
    if (tx < 256) {
        int o  = tx >> 7;
        int n2 = tx & 127;
        float p = res[128 + n2] * nw2[n2 * 2 + o];
        #pragma unroll
        for (int off = 16; off >= 1; off >>= 1)
            p += __shfl_xor_sync(0xffffffffu, p, off);
        if ((tx & 31) == 0) red_s[64 + (tx >> 5)] = p;
    }
    __syncthreads();
    if (tx == 0)   o_s[0] = nb2[0] + ((red_s[64] + red_s[65]) + (red_s[66] + red_s[67]));
    if (tx == 128) o_s[1] = nb2[1] + ((red_s[68] + red_s[69]) + (red_s[70] + red_s[71]));

    // ---- bitonic sort of 128 breakpoints (ascending, payload mi) ----
    __syncthreads();
    for (int kk = 2; kk <= 128; kk <<= 1) {
        for (int j = kk >> 1; j > 0; j >>= 1) {
            if (tx < 128) {
                int ixj = tx ^ j;
                if (ixj > tx) {
                    float a = bp_s[tx], c = bp_s[ixj];
                    bool up = ((tx & kk) == 0);
                    if ((a > c) == up) {
                        bp_s[tx] = c; bp_s[ixj] = a;
                        int t2 = mi_s[tx]; mi_s[tx] = mi_s[ixj]; mi_s[ixj] = t2;
                    }
                }
            }
            __syncthreads();
        }
    }

    // ---- builder (tx<256) | histogram + pad-zeroing (tx>=256) ----
    if (tx < 256) {
        int k = tx & 127;
        bool isA = (tx < 128);
        int kp = g_iperm[k];
        float w2k = iw2[k];
        float* seg = isA ? Aseg : (Aseg + SEGF);
        float r = isA ? 0.0f : ib1[k] * w2k;
        #pragma unroll 8
        for (int g = 128; g >= 1; --g) {
            seg[g * ST + kp] = r;
            int m = mi_s[g - 1];
            float w0m = w0_s[m];
            float wv = iw1[m * HID + k] * w2k;
            float coef = isA ? w0m : base_s[m];
            coef = (w0m <= 0.0f) ? coef : 0.0f;
            r = fmaf(coef, wv, r);
        }
        seg[kp] = r;
        r = 0.0f;
        #pragma unroll 8
        for (int g = 0; g < 128; ++g) {
            int m = mi_s[g];
            float w0m = w0_s[m];
            float wv = iw1[m * HID + k] * w2k;
            float coef = isA ? w0m : base_s[m];
            coef = (w0m > 0.0f) ? coef : 0.0f;
            r = fmaf(coef, wv, r);
            seg[(g + 1) * ST + kp] += r;
        }
    } else {
        // histogram of segment ids (counts are order-independent -> deterministic)
        for (int p = tx - 256; p < ROWS; p += 256) {
            int i = p / S1, j = p - i * S1;
            float tbi = xb * (steps_s[i] + 1.0f) * 0.5f;
            float rem = xmax - tbi;
            float s = fmaf(rem, (steps_s[j] + 1.0f) * 0.5f, tbi);
            int g = 0;
            #pragma unroll
            for (int stp = 64; stp >= 1; stp >>= 1) {
                int cand = g + stp;
                if (cand <= 128 && bp_s[cand - 1] < s) g = cand;
            }
            atomicAdd(&cnt_s[g], 1);
        }
        // zero the 8 pad slots per segment (pos-pad gives max(0,0)=0, tail-pad min(0,0)=0)
        int d = nposp - npos;
        for (int idx = tx - 256; idx < 129 * 8; idx += 256) {
            int g = idx >> 3, e = idx & 7;
            int slot = (e < d) ? (npos + e) : (nposp + (HID - npos) + (e - d));
            Aseg[g * ST + slot] = 0.0f;
            Aseg[SEGF + g * ST + slot] = 0.0f;
        }
    }
    __syncthreads();
    if (tx == 0) {
        int run = 0;
        for (int g = 0; g <= 128; ++g) { offs_s[g] = run; run += cnt_s[g]; }
    }
    __syncthreads();

    // ---- scatter points into segment-sorted order ----
    for (int p = tx; p < ROWS; p += NTHR) {
        int i = p / S1, j = p - i * S1;
        float tbi = xb * (steps_s[i] + 1.0f) * 0.5f;
        float rem = xmax - tbi;
        float s = fmaf(rem, (steps_s[j] + 1.0f) * 0.5f, tbi);
        float wt = cc_s[i] * cc_s[j] * rem * 0.5f;
        int g = 0;
        #pragma unroll
        for (int stp = 64; stp >= 1; stp >>= 1) {
            int cand = g + stp;
            if (cand <= 128 && bp_s[cand - 1] < s) g = cand;
        }
        int rank = atomicAdd(&offs_s[g], 1);
        *(float4*)(sorted + 4 * rank) =
            make_float4(s, wt, __int_as_float(g), __int_as_float(p));
    }
    __syncthreads();

    // ---- quad loop: lane-per-point over sorted slots (g mostly warp-uniform) ----
    const int np4 = nposp >> 2;
    for (int q = tx; q < ((ROWS + NTHR - 1) / NTHR) * NTHR; q += NTHR) {
        bool valid = (q < ROWS);
        float4 m = valid ? *(const float4*)(sorted + 4 * q)
                         : make_float4(0.0f, 0.0f, __int_as_float(0), __int_as_float(0));
        int g = __float_as_int(m.z);
        const float4* Ag = (const float4*)(Aseg + g * ST);
        const float4* Bg = (const float4*)(Aseg + SEGF + g * ST);
        float s = m.x;
        float pr0 = 0.0f, pr1 = 0.0f;
        int kq = 0;
        #pragma unroll 4
        for (; kq < np4; ++kq) {
            float4 a = Ag[kq], bb = Bg[kq];
            pr0 += fmaxf(fmaf(s, a.x, bb.x), 0.0f) + fmaxf(fmaf(s, a.y, bb.y), 0.0f);
            pr1 += fmaxf(fmaf(s, a.z, bb.z), 0.0f) + fmaxf(fmaf(s, a.w, bb.w), 0.0f);
        }
        #pragma unroll 4
        for (; kq < NK4; ++kq) {
            float4 a = Ag[kq], bb = Bg[kq];
            pr0 += fminf(fmaf(s, a.x, bb.x), 0.0f) + fminf(fmaf(s, a.y, bb.y), 0.0f);
            pr1 += fminf(fmaf(s, a.z, bb.z), 0.0f) + fminf(fmaf(s, a.w, bb.w), 0.0f);
        }
        if (valid) {
            float z = (pr0 + pr1) + ib2v;
            float f = (z > 0.0f) ? (z + 1.0f) : expf(z);   // elu(z)+1
            res[__float_as_int(m.w)] = f * m.y;
        }
    }
    __syncthreads();

    // ---- fixed-order reduction over res[0..ROWS) (deterministic) ----
    float t = 0.0f;
    for (int p = tx; p < ROWS; p += NTHR) t += res[p];
    red_s[tx] = t;
    __syncthreads();
    for (int o = 256; o > 0; o >>= 1) {
        if (tx < o) red_s[tx] += red_s[tx + o];
        __syncthreads();
    }
    if (tx == 0) {
        float outer = red_s[0] * xb * 0.5f;
        out[b] = expf(o_s[1]) * outer + o_s[0];
    }
}

// ===================== launch =====================
extern "C" void kernel_launch(void* const* d_in, const int* in_sizes, int n_in,
                              void* d_out, int out_size) {
    const float* x   = (const float*)d_in[0];
    const float* h   = (const float*)d_in[1];
    const float* iw0 = (const float*)d_in[2];
    const float* ib0 = (const float*)d_in[3];
    const float* iw1 = (const float*)d_in[4];
    const float* ib1 = (const float*)d_in[5];
    const float* iw2 = (const float*)d_in[6];
    const float* ib2 = (const float*)d_in[7];
    const float* nw0 = (const float*)d_in[8];
    const float* nb0 = (const float*)d_in[9];
    const float* nw1 = (const float*)d_in[10];
    const float* nb1 = (const float*)d_in[11];
    const float* nw2 = (const float*)d_in[12];
    const float* nb2 = (const float*)d_in[13];
    float* out = (float*)d_out;
    (void)in_sizes; (void)n_in; (void)out_size;

    const int smem_bytes = SMEM_FLOATS * (int)sizeof(float);
    cudaFuncSetAttribute(main_kernel,
                         cudaFuncAttributeMaxDynamicSharedMemorySize, smem_bytes);

    prep_kernel<<<1, 256>>>(x, iw2);
    main_kernel<<<BSZ, NTHR, smem_bytes>>>(x, h, iw0, ib0, iw1, ib1, iw2, ib2,
                                           nw0, nb0, nw1, nb1, nw2, nb2, out);
}

// round 5
// speedup vs baseline: 1.6598x; 1.5161x over previous
#include <cuda_runtime.h>
#include <math.h>

#define BSZ 256
#define IND 64
#define HID 128
#define NB 50
#define S1 51
#define ROWS (S1 * S1)          // 2601
#define ST 136                  // segment row stride in floats (= 34 float4)
#define NK4 34
#define SEGF (129 * ST)         // 17544 floats per b per array
#define CPB 8                   // quad chunks per batch element
#define PTS ((ROWS + CPB - 1) / CPB)   // 326
#define PI_D 3.14159265358979323846

// ---------------- global scratch (static device arrays) ----------------
__device__ float g_steps[S1];
__device__ float g_cc[S1];
__device__ float g_xmax;
__device__ int   g_iperm[HID];
__device__ int   g_npos;     // #k with iw2 >= 0
__device__ int   g_nposp;    // npos rounded up to multiple of 4
__device__ float g_A[BSZ * SEGF];      // ~18 MB
__device__ float g_Bv[BSZ * SEGF];     // ~18 MB
__device__ float4 g_meta[BSZ * ROWS];  // ~10.6 MB, segment-sorted per b
__device__ float g_res[BSZ * ROWS];    // per-point results (by original p)
__device__ float g_osc[BSZ * 2];       // offset, log-scale per b

// ===================== prep =====================
__global__ void prep_kernel(const float* __restrict__ x, const float* __restrict__ iw2) {
    __shared__ float st_s[S1];
    __shared__ double part[256];
    __shared__ float red[256];
    int tx = threadIdx.x;
    if (tx < S1) {
        double st = cos((double)tx * PI_D / (double)NB);
        st_s[tx] = (float)st;
        g_steps[tx] = (float)st;
    }
    double p = 0.0;
    if (tx < 255) {
        int c = tx / 5, u = tx % 5;
        for (int ie = u; ie < 26; ie += 5) {
            int i = 2 * ie;
            double W = (i == 0) ? 1.0 : 2.0 / (1.0 - (double)i * (double)i);
            double l;
            if (c == 0) l = 0.5;
            else {
                l = cos((double)i * (double)c * PI_D / (double)NB);
                if (c == NB) l *= 0.5;
            }
            p += l * (2.0 / (double)NB) * W;
        }
    }
    part[tx] = p;
    __syncthreads();
    if (tx < S1) {
        double s = 0.0;
        for (int u = 0; u < 5; u++) s += part[tx * 5 + u];
        g_cc[tx] = (float)s;
    }
    float mx = -3.0e38f;
    if (tx < BSZ) {
        float xb = x[tx];
        for (int i = 0; i < S1; i++)
            mx = fmaxf(mx, xb * (st_s[i] + 1.0f) * 0.5f);
    }
    red[tx] = mx;
    __syncthreads();
    for (int o = 128; o > 0; o >>= 1) {
        if (tx < o) red[tx] = fmaxf(red[tx], red[tx + o]);
        __syncthreads();
    }
    if (tx == 0) {
        g_xmax = red[0] + 10.0f;
        int P = 0;
        for (int k = 0; k < HID; k++) if (iw2[k] >= 0.0f) g_iperm[k] = P++;
        g_npos = P;
        int Pp = (P + 3) & ~3;
        g_nposp = Pp;
        int Q = Pp;
        for (int k = 0; k < HID; k++) if (iw2[k] < 0.0f)  g_iperm[k] = Q++;
    }
}

// ===================== build: per-b setup, segments + sorted meta to global =====================
__global__ void __launch_bounds__(256, 2)
build_kernel(const float* __restrict__ x,   const float* __restrict__ h,
             const float* __restrict__ iw0, const float* __restrict__ ib0,
             const float* __restrict__ iw1, const float* __restrict__ ib1,
             const float* __restrict__ iw2,
             const float* __restrict__ nw0, const float* __restrict__ nb0,
             const float* __restrict__ nw1, const float* __restrict__ nb1,
             const float* __restrict__ nw2, const float* __restrict__ nb2)
{
    __shared__ float h_s[64];
    __shared__ float base_s[128];
    __shared__ float w0_s[128];
    __shared__ float bp_s[128];
    __shared__ int   mi_s[128];
    __shared__ int   cnt_s[132];
    __shared__ int   offs_s[132];
    __shared__ float steps_s[64];
    __shared__ float cc_s[64];
    __shared__ float a_s[128];
    __shared__ float a2_s[128];
    __shared__ float red_s[8];

    const int tx = threadIdx.x;
    const int b  = blockIdx.x;
    const float xb   = x[b];
    const float xmax = g_xmax;
    const int   npos  = g_npos;
    const int   nposp = g_nposp;

    if (tx < IND - 1) h_s[tx] = h[b * (IND - 1) + tx];
    if (tx < S1) { steps_s[tx] = g_steps[tx]; cc_s[tx] = g_cc[tx]; }
    if (tx >= 64 && tx < 64 + 132) cnt_s[tx - 64] = 0;
    __syncthreads();

    // base/breakpoints (tx<128) | nmlp layer0 (128..255)
    if (tx < HID) {
        float acc = ib0[tx];
        #pragma unroll 7
        for (int d = 0; d < IND - 1; ++d)
            acc = fmaf(h_s[d], iw0[(d + 1) * HID + tx], acc);
        base_s[tx] = acc;
        float w0m = iw0[tx];
        w0_s[tx] = w0m;
        float ss;
        if (w0m != 0.0f) ss = -acc / w0m;
        else ss = (acc > 0.0f) ? __int_as_float(0x7f800000) : __int_as_float(0xff800000);
        bp_s[tx] = ss;
        mi_s[tx] = tx;
    } else {
        int k = tx - 128;
        float acc = nb0[k];
        #pragma unroll 7
        for (int d = 0; d < IND - 1; ++d)
            acc = fmaf(h_s[d], nw0[d * HID + k], acc);
        a_s[k] = fmaxf(acc, 0.0f);
    }
    __syncthreads();
    if (tx < HID) {
        float acc = nb1[tx];
        #pragma unroll 8
        for (int m = 0; m < HID; ++m)
            acc = fmaf(a_s[m], nw1[m * HID + tx], acc);
        a2_s[tx] = fmaxf(acc, 0.0f);
    }
    __syncthreads();
    {
        int o  = tx >> 7;
        int n2 = tx & 127;
        float p = a2_s[n2] * nw2[n2 * 2 + o];
        #pragma unroll
        for (int off = 16; off >= 1; off >>= 1)
            p += __shfl_xor_sync(0xffffffffu, p, off);
        if ((tx & 31) == 0) red_s[tx >> 5] = p;
    }
    __syncthreads();
    if (tx == 0)   g_osc[2 * b]     = nb2[0] + ((red_s[0] + red_s[1]) + (red_s[2] + red_s[3]));
    if (tx == 128) g_osc[2 * b + 1] = nb2[1] + ((red_s[4] + red_s[5]) + (red_s[6] + red_s[7]));
    __syncthreads();

    // bitonic sort of 128 breakpoints (ascending, payload mi)
    for (int kk = 2; kk <= 128; kk <<= 1) {
        for (int j = kk >> 1; j > 0; j >>= 1) {
            if (tx < 128) {
                int ixj = tx ^ j;
                if (ixj > tx) {
                    float a = bp_s[tx], c = bp_s[ixj];
                    bool up = ((tx & kk) == 0);
                    if ((a > c) == up) {
                        bp_s[tx] = c; bp_s[ixj] = a;
                        int t2 = mi_s[tx]; mi_s[tx] = mi_s[ixj]; mi_s[ixj] = t2;
                    }
                }
            }
            __syncthreads();
        }
    }

    // builder: prefix vectors A_g, B_g -> global (iw2/ib1 folded, sign-permuted)
    {
        int k = tx & 127;
        bool isA = (tx < 128);
        int kp = g_iperm[k];
        float w2k = iw2[k];
        float* seg = (isA ? g_A : g_Bv) + (size_t)b * SEGF;
        float r = isA ? 0.0f : ib1[k] * w2k;
        #pragma unroll 4
        for (int g = 128; g >= 1; --g) {
            seg[g * ST + kp] = r;
            int m = mi_s[g - 1];
            float w0m = w0_s[m];
            float wv = iw1[m * HID + k] * w2k;
            float coef = isA ? w0m : base_s[m];
            coef = (w0m <= 0.0f) ? coef : 0.0f;
            r = fmaf(coef, wv, r);
        }
        seg[kp] = r;
        r = 0.0f;
        #pragma unroll 4
        for (int g = 0; g < 128; ++g) {
            int m = mi_s[g];
            float w0m = w0_s[m];
            float wv = iw1[m * HID + k] * w2k;
            float coef = isA ? w0m : base_s[m];
            coef = (w0m > 0.0f) ? coef : 0.0f;
            r = fmaf(coef, wv, r);
            seg[(g + 1) * ST + kp] += r;
        }
    }
    // zero pad slots (disjoint from builder's slots)
    {
        int d = nposp - npos;
        float* Ab = g_A  + (size_t)b * SEGF;
        float* Bb = g_Bv + (size_t)b * SEGF;
        for (int idx = tx; idx < 129 * 8; idx += 256) {
            int g = idx >> 3, e = idx & 7;
            int slot = (e < d) ? (npos + e) : (nposp + (HID - npos) + (e - d));
            Ab[g * ST + slot] = 0.0f;
            Bb[g * ST + slot] = 0.0f;
        }
    }

    // histogram of segment ids
    for (int p = tx; p < ROWS; p += 256) {
        int i = p / S1, j = p - i * S1;
        float tbi = xb * (steps_s[i] + 1.0f) * 0.5f;
        float rem = xmax - tbi;
        float s = fmaf(rem, (steps_s[j] + 1.0f) * 0.5f, tbi);
        int g = 0;
        #pragma unroll
        for (int stp = 64; stp >= 1; stp >>= 1) {
            int cand = g + stp;
            if (cand <= 128 && bp_s[cand - 1] < s) g = cand;
        }
        atomicAdd(&cnt_s[g], 1);
    }
    __syncthreads();
    if (tx == 0) {
        int run = 0;
        for (int g = 0; g <= 128; ++g) { offs_s[g] = run; run += cnt_s[g]; }
    }
    __syncthreads();

    // scatter points into segment-sorted meta (rank order nondeterministic, but
    // every point's value is a pure function of its own data -> output deterministic)
    for (int p = tx; p < ROWS; p += 256) {
        int i = p / S1, j = p - i * S1;
        float tbi = xb * (steps_s[i] + 1.0f) * 0.5f;
        float rem = xmax - tbi;
        float s = fmaf(rem, (steps_s[j] + 1.0f) * 0.5f, tbi);
        float wt = cc_s[i] * cc_s[j] * rem * 0.5f;
        int g = 0;
        #pragma unroll
        for (int stp = 64; stp >= 1; stp >>= 1) {
            int cand = g + stp;
            if (cand <= 128 && bp_s[cand - 1] < s) g = cand;
        }
        int rank = atomicAdd(&offs_s[g], 1);
        int pk = (g << 12) | p;
        g_meta[b * ROWS + rank] = make_float4(s, wt, __int_as_float(pk), 0.0f);
    }
}

// ===================== quad: evaluate all points, high occupancy =====================
__global__ void __launch_bounds__(128)
quad_kernel(const float* __restrict__ ib2)
{
    const int b     = blockIdx.x >> 3;     // CPB = 8
    const int chunk = blockIdx.x & 7;
    const int np4   = g_nposp >> 2;
    const float ib2v = __ldg(ib2);
    const float4* Abase = (const float4*)(g_A  + (size_t)b * SEGF);
    const float4* Bbase = (const float4*)(g_Bv + (size_t)b * SEGF);
    float* resb = g_res + b * ROWS;

    const int qend = min((chunk + 1) * PTS, ROWS);
    for (int q = chunk * PTS + (int)threadIdx.x; q < qend; q += 128) {
        float4 m = __ldg(&g_meta[b * ROWS + q]);
        int pk = __float_as_int(m.z);
        int g = pk >> 12, p = pk & 4095;
        const float4* Ag = Abase + g * NK4;
        const float4* Bg = Bbase + g * NK4;
        float s = m.x;
        float pr0 = 0.0f, pr1 = 0.0f;
        int kq = 0;
        #pragma unroll 4
        for (; kq < np4; ++kq) {
            float4 a = __ldg(Ag + kq), bb = __ldg(Bg + kq);
            pr0 += fmaxf(fmaf(s, a.x, bb.x), 0.0f) + fmaxf(fmaf(s, a.y, bb.y), 0.0f);
            pr1 += fmaxf(fmaf(s, a.z, bb.z), 0.0f) + fmaxf(fmaf(s, a.w, bb.w), 0.0f);
        }
        #pragma unroll 4
        for (; kq < NK4; ++kq) {
            float4 a = __ldg(Ag + kq), bb = __ldg(Bg + kq);
            pr0 += fminf(fmaf(s, a.x, bb.x), 0.0f) + fminf(fmaf(s, a.y, bb.y), 0.0f);
            pr1 += fminf(fmaf(s, a.z, bb.z), 0.0f) + fminf(fmaf(s, a.w, bb.w), 0.0f);
        }
        float z = (pr0 + pr1) + ib2v;
        float f = (z > 0.0f) ? (z + 1.0f) : expf(z);   // elu(z)+1
        resb[p] = f * m.y;
    }
}

// ===================== finish: deterministic fixed-order reduction =====================
__global__ void finish_kernel(const float* __restrict__ x, float* __restrict__ out) {
    __shared__ float red[256];
    const int b = blockIdx.x, tx = threadIdx.x;
    float t = 0.0f;
    for (int p = tx; p < ROWS; p += 256) t += g_res[b * ROWS + p];
    red[tx] = t;
    __syncthreads();
    for (int o = 128; o > 0; o >>= 1) {
        if (tx < o) red[tx] += red[tx + o];
        __syncthreads();
    }
    if (tx == 0) {
        float outer = red[0] * x[b] * 0.5f;
        out[b] = expf(g_osc[2 * b + 1]) * outer + g_osc[2 * b];
    }
}

// ===================== launch =====================
extern "C" void kernel_launch(void* const* d_in, const int* in_sizes, int n_in,
                              void* d_out, int out_size) {
    const float* x   = (const float*)d_in[0];
    const float* h   = (const float*)d_in[1];
    const float* iw0 = (const float*)d_in[2];
    const float* ib0 = (const float*)d_in[3];
    const float* iw1 = (const float*)d_in[4];
    const float* ib1 = (const float*)d_in[5];
    const float* iw2 = (const float*)d_in[6];
    const float* ib2 = (const float*)d_in[7];
    const float* nw0 = (const float*)d_in[8];
    const float* nb0 = (const float*)d_in[9];
    const float* nw1 = (const float*)d_in[10];
    const float* nb1 = (const float*)d_in[11];
    const float* nw2 = (const float*)d_in[12];
    const float* nb2 = (const float*)d_in[13];
    float* out = (float*)d_out;
    (void)in_sizes; (void)n_in; (void)out_size;

    prep_kernel<<<1, 256>>>(x, iw2);
    build_kernel<<<BSZ, 256>>>(x, h, iw0, ib0, iw1, ib1, iw2,
                               nw0, nb0, nw1, nb1, nw2, nb2);
    quad_kernel<<<BSZ * CPB, 128>>>(ib2);
    finish_kernel<<<BSZ, 256>>>(x, out);
}